// round 14
// baseline (speedup 1.0000x reference)
#include <cuda_runtime.h>
#include <cuda_fp16.h>
#include <cstdint>
#include <math.h>

#define VV   32000
#define EE   512
#define HH   512
#define MIDD 128
#define BB   16
#define SS   512

// scratch (device globals: no runtime allocation allowed)
__device__ float  g_Zx[BB * SS * MIDD];     // 4 MB
__device__ __half g_out16[BB * SS * EE];    // 8 MB
__device__ __half g_embed16[VV * EE];       // 32 MB
__device__ unsigned int g_zx_done;          // 192 when zx chunks 1-3 written
__device__ unsigned int g_cvt_done;         // 64 when embed16 written
__device__ unsigned int g_rnn_done;         // +64 per completed rnn t-chunk

// ---------------------------------------------------------------- helpers
__device__ __forceinline__ void cluster_sync_all() {
    asm volatile("barrier.cluster.arrive.aligned;" ::: "memory");
    asm volatile("barrier.cluster.wait.aligned;" ::: "memory");
}
__device__ __forceinline__ uint32_t mapa_rank(uint32_t saddr, uint32_t rank) {
    uint32_t pa;
    asm volatile("mapa.shared::cluster.u32 %0, %1, %2;" : "=r"(pa) : "r"(saddr), "r"(rank));
    return pa;
}
__device__ __forceinline__ void st_async_remote(uint32_t daddr, float v, uint32_t dbar) {
    asm volatile("st.async.shared::cluster.mbarrier::complete_tx::bytes.u32 [%0], %1, [%2];"
                 :: "r"(daddr), "r"(__float_as_uint(v)), "r"(dbar) : "memory");
}
__device__ __forceinline__ void mbar_init(uint32_t a, uint32_t cnt) {
    asm volatile("mbarrier.init.shared.b64 [%0], %1;" :: "r"(a), "r"(cnt) : "memory");
}
__device__ __forceinline__ void mbar_expect_tx(uint32_t a, uint32_t bytes) {
    asm volatile("mbarrier.arrive.expect_tx.shared.b64 _, [%0], %1;"
                 :: "r"(a), "r"(bytes) : "memory");
}
__device__ __forceinline__ void mbar_wait(uint32_t a, uint32_t parity) {
    uint32_t done;
    asm volatile("{\n\t.reg .pred p;\n\t"
                 "mbarrier.try_wait.parity.acquire.cta.shared::cta.b64 p, [%1], %2;\n\t"
                 "selp.b32 %0, 1, 0, p;\n\t}"
                 : "=r"(done) : "r"(a), "r"(parity) : "memory");
    if (!done) {
        asm volatile("{\n\t.reg .pred P1;\n\t"
                     "WAIT_LOOP_%=:\n\t"
                     "mbarrier.try_wait.parity.acquire.cta.shared::cta.b64 P1, [%0], %1, 0x989680;\n\t"
                     "@P1 bra.uni WAIT_DONE_%=;\n\t"
                     "bra.uni WAIT_LOOP_%=;\n\t"
                     "WAIT_DONE_%=:\n\t}"
                     :: "r"(a), "r"(parity) : "memory");
    }
}
__device__ __forceinline__ void ldsm_x4(uint32_t& r0, uint32_t& r1, uint32_t& r2,
                                        uint32_t& r3, uint32_t a) {
    asm volatile("ldmatrix.sync.aligned.m8n8.x4.shared.b16 {%0,%1,%2,%3}, [%4];"
                 : "=r"(r0), "=r"(r1), "=r"(r2), "=r"(r3) : "r"(a));
}
__device__ __forceinline__ void mma16816(float* c, const uint32_t* a, uint32_t b0, uint32_t b1) {
    asm volatile("mma.sync.aligned.m16n8k16.row.col.f32.f16.f16.f32 "
                 "{%0,%1,%2,%3},{%4,%5,%6,%7},{%8,%9},{%0,%1,%2,%3};"
                 : "+f"(c[0]), "+f"(c[1]), "+f"(c[2]), "+f"(c[3])
                 : "r"(a[0]), "r"(a[1]), "r"(a[2]), "r"(a[3]), "r"(b0), "r"(b1));
}
__device__ __forceinline__ void cp16(uint32_t s, const void* g) {
    asm volatile("cp.async.cg.shared.global [%0], [%1], 16;" :: "r"(s), "l"(g));
}
__device__ __forceinline__ unsigned ld_acq(const unsigned* p) {
    unsigned v;
    asm volatile("ld.acquire.gpu.global.u32 %0, [%1];" : "=r"(v) : "l"(p) : "memory");
    return v;
}
__device__ __forceinline__ void red_rel(unsigned* p) {
    asm volatile("red.release.gpu.global.add.u32 [%0], 1;" :: "l"(p) : "memory");
}
__device__ __forceinline__ void spin_until(const unsigned* p, unsigned target) {
    while (ld_acq(p) < target) {
        asm volatile("nanosleep.u32 128;");
    }
}

// ---------------------------------------------------------------- zx body (256 thr; tid>=128 idles through barriers)
__device__ __forceinline__ void zx_body(const int* __restrict__ ids,
                                        const float* __restrict__ embed,
                                        const float* __restrict__ W1,
                                        const float* __restrict__ b1,
                                        int token0) {
    __shared__ float xs[32][64];
    __shared__ float ws[64][MIDD];
    __shared__ int   sid[32];
    const int tid = threadIdx.x;

    if (tid < 32) sid[tid] = ids[token0 + tid];
    __syncthreads();

    float acc[32];
#pragma unroll
    for (int m = 0; m < 32; m++) acc[m] = 0.f;

    for (int kt = 0; kt < 8; kt++) {
        const int k0 = kt * 64;
        if (tid < 128) {
#pragma unroll
            for (int i = 0; i < 4; i++) {
                int j = tid + i * 128, m = j >> 4, q = j & 15;
                *reinterpret_cast<float4*>(&xs[m][q * 4]) =
                    *reinterpret_cast<const float4*>(&embed[(size_t)sid[m] * EE + k0 + q * 4]);
            }
#pragma unroll
            for (int i = 0; i < 16; i++) {
                int j = tid + i * 128, k = j >> 5, q = j & 31;
                *reinterpret_cast<float4*>(&ws[k][q * 4]) =
                    *reinterpret_cast<const float4*>(&W1[(size_t)(k0 + k) * MIDD + q * 4]);
            }
        }
        __syncthreads();
        if (tid < 128) {
#pragma unroll 4
            for (int kk = 0; kk < 64; kk += 4) {
                float w0 = ws[kk + 0][tid], w1 = ws[kk + 1][tid];
                float w2 = ws[kk + 2][tid], w3 = ws[kk + 3][tid];
#pragma unroll
                for (int m = 0; m < 32; m++) {
                    float4 x4 = *reinterpret_cast<const float4*>(&xs[m][kk]);
                    float a = acc[m];
                    a = fmaf(x4.x, w0, a); a = fmaf(x4.y, w1, a);
                    a = fmaf(x4.z, w2, a); a = fmaf(x4.w, w3, a);
                    acc[m] = a;
                }
            }
        }
        __syncthreads();
    }
    if (tid < 128) {
        const float bb = b1[tid];
#pragma unroll
        for (int m = 0; m < 32; m++)
            g_Zx[(size_t)(token0 + m) * MIDD + tid] = acc[m] + bb;
    }
}

// zx chunk c covers t in [128c, 128c+128) for all 16 batches.
__device__ __forceinline__ int zx_token0(int chunk, int i) {
    return (i >> 2) * SS + chunk * 128 + (i & 3) * 32;
}

// ---------------------------------------------------------------- cvt body
__device__ __forceinline__ void cvt_body(const float* __restrict__ src, int bid, int nblocks) {
    int i = bid * (int)blockDim.x + (int)threadIdx.x;
    int stride = nblocks * (int)blockDim.x;
    const int n4 = (VV * EE) / 4;
    __half2* dst = reinterpret_cast<__half2*>(g_embed16);
    const float4* s4 = reinterpret_cast<const float4*>(src);
    for (; i < n4; i += stride) {
        float4 v = s4[i];
        dst[2 * i + 0] = __floats2half2_rn(v.x, v.y);
        dst[2 * i + 1] = __floats2half2_rn(v.z, v.w);
    }
}

// ---------------------------------------------------------------- persistent rnn body (512 steps, 256 thr)
#define NBUF 4
__device__ __forceinline__ void rnn_full(const float* __restrict__ hidden,
                                         const float* __restrict__ W1,
                                         const float* __restrict__ W2) {
    __shared__ __align__(16) float h_loc[128];
    __shared__ __align__(16) float g_s[128];
    __shared__ __align__(16) float zparts[NBUF][4][128];
    __shared__ __align__(8)  unsigned long long mbar[NBUF];

    const int tid  = threadIdx.x;
    const int b    = blockIdx.x >> 2;
    const int c    = tid >> 1;
    const int half = tid & 1;
    uint32_t rank;
    asm("mov.u32 %0, %%cluster_ctarank;" : "=r"(rank));

    float w1z[64], w2h[64];
#pragma unroll
    for (int i = 0; i < 64; i++)
        w1z[i] = W1[(size_t)(HH + 128 * rank + 64 * half + i) * MIDD + c];
#pragma unroll
    for (int i = 0; i < 64; i++)
        w2h[i] = W2[(size_t)(64 * half + i) * EE + 128 * rank + c];

    const uint32_t zp_loc  = (uint32_t)__cvta_generic_to_shared(&zparts[0][0][0]);
    const uint32_t bar_loc = (uint32_t)__cvta_generic_to_shared(&mbar[0]);

    if (tid == 0) {
#pragma unroll
        for (int s = 0; s < NBUF; s++) mbar_init(bar_loc + 8u * s, 1);
    }
    if (tid < 128) h_loc[tid] = hidden[(size_t)b * HH + 128 * rank + tid];
    __syncthreads();
    cluster_sync_all();

    uint32_t zp_dst[4], bar_dst[4];
#pragma unroll
    for (int r = 0; r < 4; r++) {
        zp_dst[r]  = mapa_rank(zp_loc, r);
        bar_dst[r] = mapa_rank(bar_loc, r);
    }

    const float* zx_row  = g_Zx    + (size_t)b * SS * MIDD;
    __half*      out_row = g_out16 + (size_t)b * SS * EE + 128 * rank;
    float zx_cur = (tid < 128) ? zx_row[tid] : 0.f;

    for (int t = 0; t < SS; t++) {
        const int buf = t & (NBUF - 1);
        const uint32_t ph = (uint32_t)((t >> 2) & 1);

        // gate before consuming zx chunks 1..3 (prefetch of t+1 happens this step)
        if (((t & 127) == 127) && t != 511) spin_until(&g_zx_done, 192u);

        if (tid == 0) mbar_expect_tx(bar_loc + 8u * buf, 4 * 128 * 4);

        float a0 = 0.f, a1 = 0.f, a2 = 0.f, a3 = 0.f;
#pragma unroll
        for (int i = 0; i < 64; i += 4) {
            float4 h4 = *reinterpret_cast<const float4*>(&h_loc[64 * half + i]);
            a0 = fmaf(h4.x, w1z[i + 0], a0);
            a1 = fmaf(h4.y, w1z[i + 1], a1);
            a2 = fmaf(h4.z, w1z[i + 2], a2);
            a3 = fmaf(h4.w, w1z[i + 3], a3);
        }
        float part = (a0 + a1) + (a2 + a3);
        part += __shfl_xor_sync(0xffffffffu, part, 1);

        if (half == 0) {
            const uint32_t off = (uint32_t)((buf * 4 + rank) * 128 + c) * 4u;
#pragma unroll
            for (int r = 0; r < 4; r++)
                st_async_remote(zp_dst[r] + off, part, bar_dst[r] + 8u * buf);
        }

        mbar_wait(bar_loc + 8u * buf, ph);

        if (tid < 128) {
            const float* zp = &zparts[buf][0][tid];
            float z = zx_cur + ((zp[0] + zp[128]) + (zp[256] + zp[384]));
            g_s[tid] = 0.5f * z * (1.0f + erff(z * 0.70710678118f));
            if (t + 1 < SS) zx_cur = zx_row[(size_t)(t + 1) * MIDD + tid];
        }
        __syncthreads();

        float b0 = 0.f, b1a = 0.f, b2 = 0.f, b3 = 0.f;
#pragma unroll
        for (int i = 0; i < 64; i += 4) {
            float4 g4 = *reinterpret_cast<const float4*>(&g_s[64 * half + i]);
            b0  = fmaf(g4.x, w2h[i + 0], b0);
            b1a = fmaf(g4.y, w2h[i + 1], b1a);
            b2  = fmaf(g4.z, w2h[i + 2], b2);
            b3  = fmaf(g4.w, w2h[i + 3], b3);
        }
        float hp = (b0 + b1a) + (b2 + b3);
        hp += __shfl_xor_sync(0xffffffffu, hp, 1);
        if (half == 0) {
            h_loc[c] = hp;
            out_row[(size_t)t * EE + c] = __float2half_rn(hp);
        }
        __syncthreads();

        // publish completed t-chunk (stores ordered by the barrier above)
        if (((t & 127) == 127) && tid == 0) red_rel(&g_rnn_done);
    }
    cluster_sync_all();
}

// ---------------------------------------------------------------- gemm body — R8 exact
#define ASTRIDE 72                       // halves per smem row (144B)
#define A_ST    (128 * ASTRIDE)
#define B_ST    (256 * ASTRIDE)
#define GSMEM   ((3 * (A_ST + B_ST)) * 2)   // 165888 B

__device__ __forceinline__ void gemm_body(const float* __restrict__ cls_b,
                                          float* __restrict__ C,
                                          int gb, int chunk) {
    extern __shared__ __align__(16) __half sm[];
    __half* As = sm;
    __half* Bs = sm + 3 * A_ST;

    const int tid = threadIdx.x;
    const int wid = tid >> 5, lane = tid & 31;
    const int bidx = gb / 125, nb = gb % 125;
    const int R0 = bidx * SS + chunk * 128;
    const int N0 = nb * 256;

    const __half* Ag = g_out16   + (size_t)R0 * EE;
    const __half* Bg = g_embed16 + (size_t)N0 * EE;

    const int warp_m = (wid >> 2) * 64;
    const int warp_n = (wid & 3) * 64;

    float c[4][8][4];
#pragma unroll
    for (int i = 0; i < 4; i++)
#pragma unroll
        for (int j = 0; j < 8; j++)
#pragma unroll
            for (int q = 0; q < 4; q++) c[i][j][q] = 0.f;

    const uint32_t asb = (uint32_t)__cvta_generic_to_shared(As);
    const uint32_t bsb = (uint32_t)__cvta_generic_to_shared(Bs);

    auto load_tile = [&](int kt, int st) {
        const uint32_t ab = asb + (uint32_t)(st * A_ST) * 2;
        const uint32_t bb = bsb + (uint32_t)(st * B_ST) * 2;
#pragma unroll
        for (int i = 0; i < 4; i++) {           // A: 1024 chunks of 16B
            int cc = tid + i * 256;
            int r = cc >> 3, sg = cc & 7;
            cp16(ab + (uint32_t)(r * ASTRIDE + sg * 8) * 2,
                 Ag + (size_t)r * EE + kt * 64 + sg * 8);
        }
#pragma unroll
        for (int i = 0; i < 8; i++) {           // B: 2048 chunks of 16B
            int cc = tid + i * 256;
            int r = cc >> 3, sg = cc & 7;
            cp16(bb + (uint32_t)(r * ASTRIDE + sg * 8) * 2,
                 Bg + (size_t)r * EE + kt * 64 + sg * 8);
        }
        asm volatile("cp.async.commit_group;");
    };

    uint32_t afr[2][4][4], bfr[2][8][2];

    auto ldsm_batch = [&](int kk, uint32_t ab, uint32_t bb, int pb) {
        const uint32_t koff = (uint32_t)(kk * 16 + ((lane >> 4) << 3));
#pragma unroll
        for (int i = 0; i < 4; i++) {
            uint32_t addr = ab + (uint32_t)((warp_m + i * 16 + (lane & 15)) * ASTRIDE + koff) * 2;
            ldsm_x4(afr[pb][i][0], afr[pb][i][1], afr[pb][i][2], afr[pb][i][3], addr);
        }
#pragma unroll
        for (int j2 = 0; j2 < 4; j2++) {
            uint32_t r0, r1, r2, r3;
            uint32_t addr = bb + (uint32_t)((warp_n + j2 * 16 + (lane & 15)) * ASTRIDE + koff) * 2;
            ldsm_x4(r0, r1, r2, r3, addr);
            bfr[pb][2 * j2 + 0][0] = r0; bfr[pb][2 * j2 + 0][1] = r2;
            bfr[pb][2 * j2 + 1][0] = r1; bfr[pb][2 * j2 + 1][1] = r3;
        }
    };

    load_tile(0, 0);
    load_tile(1, 1);

    for (int kt = 0; kt < 8; kt++) {
        const int st = kt % 3;
        if (kt < 7) asm volatile("cp.async.wait_group 1;");
        else        asm volatile("cp.async.wait_group 0;");
        __syncthreads();

        if (kt + 2 < 8) load_tile(kt + 2, (kt + 2) % 3);

        const uint32_t ab = asb + (uint32_t)(st * A_ST) * 2;
        const uint32_t bb = bsb + (uint32_t)(st * B_ST) * 2;

        ldsm_batch(0, ab, bb, 0);
#pragma unroll
        for (int kk = 0; kk < 4; kk++) {
            const int cur = kk & 1;
            if (kk < 3) ldsm_batch(kk + 1, ab, bb, cur ^ 1);
#pragma unroll
            for (int i = 0; i < 4; i++)
#pragma unroll
                for (int j = 0; j < 8; j++)
                    mma16816(c[i][j], afr[cur][i], bfr[cur][j][0], bfr[cur][j][1]);
        }
        __syncthreads();
    }

#pragma unroll
    for (int i = 0; i < 4; i++) {
        int rm0 = R0 + warp_m + i * 16 + (lane >> 2);
#pragma unroll
        for (int j = 0; j < 8; j++) {
            int gn = N0 + warp_n + j * 8 + (lane & 3) * 2;
            float2 bv = *reinterpret_cast<const float2*>(&cls_b[gn]);
            float2 v0 = make_float2(c[i][j][0] + bv.x, c[i][j][1] + bv.y);
            float2 v1 = make_float2(c[i][j][2] + bv.x, c[i][j][3] + bv.y);
            *reinterpret_cast<float2*>(&C[(size_t)rm0 * VV + gn])       = v0;
            *reinterpret_cast<float2*>(&C[(size_t)(rm0 + 8) * VV + gn]) = v1;
        }
    }
}

// ---------------------------------------------------------------- mega kernel
// mode 0 (L0, 64 blocks): zero counters + zx chunk 0.
// mode 1 (L1, 8320 blocks):
//   bid [0,64)      : persistent rnn (512 steps), releases g_rnn_done per chunk
//   bid [64,256)    : zx chunks 1..3  -> g_zx_done
//   bid [256,320)   : embed cvt       -> g_cvt_done
//   bid [320,8320)  : gemm tile, gated on g_cvt_done==64 && g_rnn_done>=64*(chunk+1)
__global__ void __cluster_dims__(4, 1, 1) __launch_bounds__(256, 1)
mega_kernel(const float* __restrict__ hidden,
            const float* __restrict__ W1,
            const float* __restrict__ W2,
            const float* __restrict__ cls_b,
            const float* __restrict__ embed,
            const int*   __restrict__ ids,
            const float* __restrict__ b1,
            float* __restrict__ C,
            int mode) {
    const int bid = (int)blockIdx.x;
    const int tid = (int)threadIdx.x;

    if (mode == 0) {
        if (bid == 0 && tid == 0) {
            g_zx_done = 0; g_cvt_done = 0; g_rnn_done = 0;
        }
        zx_body(ids, embed, W1, b1, zx_token0(0, bid));
        return;
    }

    if (bid < 64) {
        rnn_full(hidden, W1, W2);
    } else if (bid < 256) {
        int j = bid - 64;
        zx_body(ids, embed, W1, b1, zx_token0(1 + j / 64, j % 64));
        __syncthreads();
        if (tid == 0) red_rel(&g_zx_done);
    } else if (bid < 320) {
        cvt_body(embed, bid - 256, 64);
        __syncthreads();
        if (tid == 0) red_rel(&g_cvt_done);
    } else {
        const int gb = bid - 320;
        const int chunk = gb / 2000;
        const int g = gb % 2000;
        if (tid == 0) {
            spin_until(&g_cvt_done, 64u);
            spin_until(&g_rnn_done, (unsigned)(64 * (chunk + 1)));
        }
        __syncthreads();
        gemm_body(cls_b, C, g, chunk);
    }
}

// ---------------------------------------------------------------- launch
extern "C" void kernel_launch(void* const* d_in, const int* in_sizes, int n_in,
                              void* d_out, int out_size) {
    const int*   ids    = (const int*)d_in[0];
    const float* hidden = (const float*)d_in[1];
    const float* embed  = (const float*)d_in[2];
    const float* W1     = (const float*)d_in[3];
    const float* b1     = (const float*)d_in[4];
    const float* W2     = (const float*)d_in[5];
    const float* cls_b  = (const float*)d_in[6];
    float* out = (float*)d_out;

    cudaFuncSetAttribute(mega_kernel, cudaFuncAttributeMaxDynamicSharedMemorySize, GSMEM);

    // L0: counter reset + zx chunk 0
    mega_kernel<<<64, 256, GSMEM>>>(hidden, W1, W2, cls_b, embed, ids, b1, out, 0);
    // L1: everything else, flag-gated
    mega_kernel<<<8320, 256, GSMEM>>>(hidden, W1, W2, cls_b, embed, ids, b1, out, 1);
}

// round 15
// speedup vs baseline: 1.0014x; 1.0014x over previous
#include <cuda_runtime.h>
#include <cuda_fp16.h>
#include <cstdint>
#include <math.h>

#define VV   32000
#define EE   512
#define HH   512
#define MIDD 128
#define BB   16
#define SS   512

// scratch (device globals: no runtime allocation allowed)
__device__ float  g_Zx[BB * SS * MIDD];     // 4 MB
__device__ __half g_out16[BB * SS * EE];    // 8 MB
__device__ __half g_embed16[VV * EE];       // 32 MB
__device__ unsigned int g_zx0_done;         // 64 when zx chunk 0 written
__device__ unsigned int g_zx_done;          // 192 when zx chunks 1-3 written
__device__ unsigned int g_cvt_done;         // 64 when embed16 written
__device__ unsigned int g_rnn_done;         // +64 per completed rnn t-chunk

// ---------------------------------------------------------------- helpers
__device__ __forceinline__ void cluster_sync_all() {
    asm volatile("barrier.cluster.arrive.aligned;" ::: "memory");
    asm volatile("barrier.cluster.wait.aligned;" ::: "memory");
}
__device__ __forceinline__ uint32_t mapa_rank(uint32_t saddr, uint32_t rank) {
    uint32_t pa;
    asm volatile("mapa.shared::cluster.u32 %0, %1, %2;" : "=r"(pa) : "r"(saddr), "r"(rank));
    return pa;
}
__device__ __forceinline__ void st_async_remote64(uint32_t daddr, unsigned long long v, uint32_t dbar) {
    asm volatile("st.async.shared::cluster.mbarrier::complete_tx::bytes.u64 [%0], %1, [%2];"
                 :: "r"(daddr), "l"(v), "r"(dbar) : "memory");
}
__device__ __forceinline__ void mbar_init(uint32_t a, uint32_t cnt) {
    asm volatile("mbarrier.init.shared.b64 [%0], %1;" :: "r"(a), "r"(cnt) : "memory");
}
__device__ __forceinline__ void mbar_expect_tx(uint32_t a, uint32_t bytes) {
    asm volatile("mbarrier.arrive.expect_tx.shared.b64 _, [%0], %1;"
                 :: "r"(a), "r"(bytes) : "memory");
}
__device__ __forceinline__ void mbar_wait(uint32_t a, uint32_t parity) {
    uint32_t done;
    asm volatile("{\n\t.reg .pred p;\n\t"
                 "mbarrier.try_wait.parity.acquire.cta.shared::cta.b64 p, [%1], %2;\n\t"
                 "selp.b32 %0, 1, 0, p;\n\t}"
                 : "=r"(done) : "r"(a), "r"(parity) : "memory");
    if (!done) {
        asm volatile("{\n\t.reg .pred P1;\n\t"
                     "WAIT_LOOP_%=:\n\t"
                     "mbarrier.try_wait.parity.acquire.cta.shared::cta.b64 P1, [%0], %1, 0x989680;\n\t"
                     "@P1 bra.uni WAIT_DONE_%=;\n\t"
                     "bra.uni WAIT_LOOP_%=;\n\t"
                     "WAIT_DONE_%=:\n\t}"
                     :: "r"(a), "r"(parity) : "memory");
    }
}
__device__ __forceinline__ void ldsm_x4(uint32_t& r0, uint32_t& r1, uint32_t& r2,
                                        uint32_t& r3, uint32_t a) {
    asm volatile("ldmatrix.sync.aligned.m8n8.x4.shared.b16 {%0,%1,%2,%3}, [%4];"
                 : "=r"(r0), "=r"(r1), "=r"(r2), "=r"(r3) : "r"(a));
}
__device__ __forceinline__ void mma16816(float* c, const uint32_t* a, uint32_t b0, uint32_t b1) {
    asm volatile("mma.sync.aligned.m16n8k16.row.col.f32.f16.f16.f32 "
                 "{%0,%1,%2,%3},{%4,%5,%6,%7},{%8,%9},{%0,%1,%2,%3};"
                 : "+f"(c[0]), "+f"(c[1]), "+f"(c[2]), "+f"(c[3])
                 : "r"(a[0]), "r"(a[1]), "r"(a[2]), "r"(a[3]), "r"(b0), "r"(b1));
}
__device__ __forceinline__ void cp16(uint32_t s, const void* g) {
    asm volatile("cp.async.cg.shared.global [%0], [%1], 16;" :: "r"(s), "l"(g));
}
__device__ __forceinline__ unsigned ld_acq(const unsigned* p) {
    unsigned v;
    asm volatile("ld.acquire.gpu.global.u32 %0, [%1];" : "=r"(v) : "l"(p) : "memory");
    return v;
}
__device__ __forceinline__ void red_rel(unsigned* p) {
    asm volatile("red.release.gpu.global.add.u32 [%0], 1;" :: "l"(p) : "memory");
}
__device__ __forceinline__ void spin_until(const unsigned* p, unsigned target) {
    while (ld_acq(p) < target) {
        asm volatile("nanosleep.u32 128;");
    }
}

// ---------------------------------------------------------------- zx body (256 thr; tid>=128 idles through barriers)
__device__ __forceinline__ void zx_body(const int* __restrict__ ids,
                                        const float* __restrict__ embed,
                                        const float* __restrict__ W1,
                                        const float* __restrict__ b1,
                                        int token0) {
    __shared__ float xs[32][64];
    __shared__ float ws[64][MIDD];
    __shared__ int   sid[32];
    const int tid = threadIdx.x;

    if (tid < 32) sid[tid] = ids[token0 + tid];
    __syncthreads();

    float acc[32];
#pragma unroll
    for (int m = 0; m < 32; m++) acc[m] = 0.f;

    for (int kt = 0; kt < 8; kt++) {
        const int k0 = kt * 64;
        if (tid < 128) {
#pragma unroll
            for (int i = 0; i < 4; i++) {
                int j = tid + i * 128, m = j >> 4, q = j & 15;
                *reinterpret_cast<float4*>(&xs[m][q * 4]) =
                    *reinterpret_cast<const float4*>(&embed[(size_t)sid[m] * EE + k0 + q * 4]);
            }
#pragma unroll
            for (int i = 0; i < 16; i++) {
                int j = tid + i * 128, k = j >> 5, q = j & 31;
                *reinterpret_cast<float4*>(&ws[k][q * 4]) =
                    *reinterpret_cast<const float4*>(&W1[(size_t)(k0 + k) * MIDD + q * 4]);
            }
        }
        __syncthreads();
        if (tid < 128) {
#pragma unroll 4
            for (int kk = 0; kk < 64; kk += 4) {
                float w0 = ws[kk + 0][tid], w1 = ws[kk + 1][tid];
                float w2 = ws[kk + 2][tid], w3 = ws[kk + 3][tid];
#pragma unroll
                for (int m = 0; m < 32; m++) {
                    float4 x4 = *reinterpret_cast<const float4*>(&xs[m][kk]);
                    float a = acc[m];
                    a = fmaf(x4.x, w0, a); a = fmaf(x4.y, w1, a);
                    a = fmaf(x4.z, w2, a); a = fmaf(x4.w, w3, a);
                    acc[m] = a;
                }
            }
        }
        __syncthreads();
    }
    if (tid < 128) {
        const float bb = b1[tid];
#pragma unroll
        for (int m = 0; m < 32; m++)
            g_Zx[(size_t)(token0 + m) * MIDD + tid] = acc[m] + bb;
    }
}

// zx chunk c covers t in [128c, 128c+128) for all 16 batches.
__device__ __forceinline__ int zx_token0(int chunk, int i) {
    return (i >> 2) * SS + chunk * 128 + (i & 3) * 32;
}

// ---------------------------------------------------------------- cvt body
__device__ __forceinline__ void cvt_body(const float* __restrict__ src, int bid, int nblocks) {
    int i = bid * (int)blockDim.x + (int)threadIdx.x;
    int stride = nblocks * (int)blockDim.x;
    const int n4 = (VV * EE) / 4;
    __half2* dst = reinterpret_cast<__half2*>(g_embed16);
    const float4* s4 = reinterpret_cast<const float4*>(src);
    for (; i < n4; i += stride) {
        float4 v = s4[i];
        dst[2 * i + 0] = __floats2half2_rn(v.x, v.y);
        dst[2 * i + 1] = __floats2half2_rn(v.z, v.w);
    }
}

// ---------------------------------------------------------------- persistent rnn body (512 steps, 256 thr)
#define NBUF 4
__device__ __forceinline__ void rnn_full(const float* __restrict__ hidden,
                                         const float* __restrict__ W1,
                                         const float* __restrict__ W2) {
    __shared__ __align__(16) float h_loc[128];
    __shared__ __align__(16) float g_s[128];
    __shared__ __align__(16) float zparts[NBUF][4][128];
    __shared__ __align__(8)  unsigned long long mbar[NBUF];

    const int tid  = threadIdx.x;
    const int b    = blockIdx.x >> 2;
    const int c    = tid >> 1;
    const int half = tid & 1;
    uint32_t rank;
    asm("mov.u32 %0, %%cluster_ctarank;" : "=r"(rank));

    float w1z[64], w2h[64];
#pragma unroll
    for (int i = 0; i < 64; i++)
        w1z[i] = W1[(size_t)(HH + 128 * rank + 64 * half + i) * MIDD + c];
#pragma unroll
    for (int i = 0; i < 64; i++)
        w2h[i] = W2[(size_t)(64 * half + i) * EE + 128 * rank + c];

    const uint32_t zp_loc  = (uint32_t)__cvta_generic_to_shared(&zparts[0][0][0]);
    const uint32_t bar_loc = (uint32_t)__cvta_generic_to_shared(&mbar[0]);

    if (tid == 0) {
#pragma unroll
        for (int s = 0; s < NBUF; s++) mbar_init(bar_loc + 8u * s, 1);
    }
    if (tid < 128) h_loc[tid] = hidden[(size_t)b * HH + 128 * rank + tid];
    __syncthreads();
    cluster_sync_all();

    uint32_t zp_dst[4], bar_dst[4];
#pragma unroll
    for (int r = 0; r < 4; r++) {
        zp_dst[r]  = mapa_rank(zp_loc, r);
        bar_dst[r] = mapa_rank(bar_loc, r);
    }

    // wait for zx chunk 0 before first read
    if (tid == 0) spin_until(&g_zx0_done, 64u);
    __syncthreads();

    const float* zx_row  = g_Zx    + (size_t)b * SS * MIDD;
    __half*      out_row = g_out16 + (size_t)b * SS * EE + 128 * rank;
    float zx_cur = (tid < 128) ? zx_row[tid] : 0.f;

    for (int t = 0; t < SS; t++) {
        const int buf = t & (NBUF - 1);
        const uint32_t ph = (uint32_t)((t >> 2) & 1);

        // gate before consuming zx chunks 1..3 (prefetch of t+1 happens this step)
        if (((t & 127) == 127) && t != 511) spin_until(&g_zx_done, 192u);

        if (tid == 0) mbar_expect_tx(bar_loc + 8u * buf, 4 * 128 * 4);

        float a0 = 0.f, a1 = 0.f, a2 = 0.f, a3 = 0.f;
#pragma unroll
        for (int i = 0; i < 64; i += 4) {
            float4 h4 = *reinterpret_cast<const float4*>(&h_loc[64 * half + i]);
            a0 = fmaf(h4.x, w1z[i + 0], a0);
            a1 = fmaf(h4.y, w1z[i + 1], a1);
            a2 = fmaf(h4.z, w1z[i + 2], a2);
            a3 = fmaf(h4.w, w1z[i + 3], a3);
        }
        float part = (a0 + a1) + (a2 + a3);
        part += __shfl_xor_sync(0xffffffffu, part, 1);
        // pair exchange: thread with even c obtains part[c+1]
        float other = __shfl_xor_sync(0xffffffffu, part, 2);

        if ((tid & 3) == 0) {           // half==0 and c even
            unsigned long long pkt;
            asm("mov.b64 %0, {%1, %2};" : "=l"(pkt)
                : "r"(__float_as_uint(part)), "r"(__float_as_uint(other)));
            const uint32_t off = (uint32_t)((buf * 4 + rank) * 128 + c) * 4u;
#pragma unroll
            for (int r = 0; r < 4; r++)
                st_async_remote64(zp_dst[r] + off, pkt, bar_dst[r] + 8u * buf);
        }

        mbar_wait(bar_loc + 8u * buf, ph);

        if (tid < 128) {
            const float* zp = &zparts[buf][0][tid];
            float z = zx_cur + ((zp[0] + zp[128]) + (zp[256] + zp[384]));
            g_s[tid] = 0.5f * z * (1.0f + erff(z * 0.70710678118f));
            if (t + 1 < SS) zx_cur = zx_row[(size_t)(t + 1) * MIDD + tid];
        }
        __syncthreads();

        float b0 = 0.f, b1a = 0.f, b2 = 0.f, b3 = 0.f;
#pragma unroll
        for (int i = 0; i < 64; i += 4) {
            float4 g4 = *reinterpret_cast<const float4*>(&g_s[64 * half + i]);
            b0  = fmaf(g4.x, w2h[i + 0], b0);
            b1a = fmaf(g4.y, w2h[i + 1], b1a);
            b2  = fmaf(g4.z, w2h[i + 2], b2);
            b3  = fmaf(g4.w, w2h[i + 3], b3);
        }
        float hp = (b0 + b1a) + (b2 + b3);
        hp += __shfl_xor_sync(0xffffffffu, hp, 1);
        if (half == 0) {
            h_loc[c] = hp;
            out_row[(size_t)t * EE + c] = __float2half_rn(hp);
        }
        __syncthreads();

        // publish completed t-chunk (stores ordered by the barrier above)
        if (((t & 127) == 127) && tid == 0) red_rel(&g_rnn_done);
    }
    cluster_sync_all();
}

// ---------------------------------------------------------------- gemm body — R8 exact
#define ASTRIDE 72                       // halves per smem row (144B)
#define A_ST    (128 * ASTRIDE)
#define B_ST    (256 * ASTRIDE)
#define GSMEM   ((3 * (A_ST + B_ST)) * 2)   // 165888 B

__device__ __forceinline__ void gemm_body(const float* __restrict__ cls_b,
                                          float* __restrict__ C,
                                          int gb, int chunk) {
    extern __shared__ __align__(16) __half sm[];
    __half* As = sm;
    __half* Bs = sm + 3 * A_ST;

    const int tid = threadIdx.x;
    const int wid = tid >> 5, lane = tid & 31;
    const int bidx = gb / 125, nb = gb % 125;
    const int R0 = bidx * SS + chunk * 128;
    const int N0 = nb * 256;

    const __half* Ag = g_out16   + (size_t)R0 * EE;
    const __half* Bg = g_embed16 + (size_t)N0 * EE;

    const int warp_m = (wid >> 2) * 64;
    const int warp_n = (wid & 3) * 64;

    float c[4][8][4];
#pragma unroll
    for (int i = 0; i < 4; i++)
#pragma unroll
        for (int j = 0; j < 8; j++)
#pragma unroll
            for (int q = 0; q < 4; q++) c[i][j][q] = 0.f;

    const uint32_t asb = (uint32_t)__cvta_generic_to_shared(As);
    const uint32_t bsb = (uint32_t)__cvta_generic_to_shared(Bs);

    auto load_tile = [&](int kt, int st) {
        const uint32_t ab = asb + (uint32_t)(st * A_ST) * 2;
        const uint32_t bb = bsb + (uint32_t)(st * B_ST) * 2;
#pragma unroll
        for (int i = 0; i < 4; i++) {           // A: 1024 chunks of 16B
            int cc = tid + i * 256;
            int r = cc >> 3, sg = cc & 7;
            cp16(ab + (uint32_t)(r * ASTRIDE + sg * 8) * 2,
                 Ag + (size_t)r * EE + kt * 64 + sg * 8);
        }
#pragma unroll
        for (int i = 0; i < 8; i++) {           // B: 2048 chunks of 16B
            int cc = tid + i * 256;
            int r = cc >> 3, sg = cc & 7;
            cp16(bb + (uint32_t)(r * ASTRIDE + sg * 8) * 2,
                 Bg + (size_t)r * EE + kt * 64 + sg * 8);
        }
        asm volatile("cp.async.commit_group;");
    };

    uint32_t afr[2][4][4], bfr[2][8][2];

    auto ldsm_batch = [&](int kk, uint32_t ab, uint32_t bb, int pb) {
        const uint32_t koff = (uint32_t)(kk * 16 + ((lane >> 4) << 3));
#pragma unroll
        for (int i = 0; i < 4; i++) {
            uint32_t addr = ab + (uint32_t)((warp_m + i * 16 + (lane & 15)) * ASTRIDE + koff) * 2;
            ldsm_x4(afr[pb][i][0], afr[pb][i][1], afr[pb][i][2], afr[pb][i][3], addr);
        }
#pragma unroll
        for (int j2 = 0; j2 < 4; j2++) {
            uint32_t r0, r1, r2, r3;
            uint32_t addr = bb + (uint32_t)((warp_n + j2 * 16 + (lane & 15)) * ASTRIDE + koff) * 2;
            ldsm_x4(r0, r1, r2, r3, addr);
            bfr[pb][2 * j2 + 0][0] = r0; bfr[pb][2 * j2 + 0][1] = r2;
            bfr[pb][2 * j2 + 1][0] = r1; bfr[pb][2 * j2 + 1][1] = r3;
        }
    };

    load_tile(0, 0);
    load_tile(1, 1);

    for (int kt = 0; kt < 8; kt++) {
        const int st = kt % 3;
        if (kt < 7) asm volatile("cp.async.wait_group 1;");
        else        asm volatile("cp.async.wait_group 0;");
        __syncthreads();

        if (kt + 2 < 8) load_tile(kt + 2, (kt + 2) % 3);

        const uint32_t ab = asb + (uint32_t)(st * A_ST) * 2;
        const uint32_t bb = bsb + (uint32_t)(st * B_ST) * 2;

        ldsm_batch(0, ab, bb, 0);
#pragma unroll
        for (int kk = 0; kk < 4; kk++) {
            const int cur = kk & 1;
            if (kk < 3) ldsm_batch(kk + 1, ab, bb, cur ^ 1);
#pragma unroll
            for (int i = 0; i < 4; i++)
#pragma unroll
                for (int j = 0; j < 8; j++)
                    mma16816(c[i][j], afr[cur][i], bfr[cur][j][0], bfr[cur][j][1]);
        }
        __syncthreads();
    }

#pragma unroll
    for (int i = 0; i < 4; i++) {
        int rm0 = R0 + warp_m + i * 16 + (lane >> 2);
#pragma unroll
        for (int j = 0; j < 8; j++) {
            int gn = N0 + warp_n + j * 8 + (lane & 3) * 2;
            float2 bv = *reinterpret_cast<const float2*>(&cls_b[gn]);
            float2 v0 = make_float2(c[i][j][0] + bv.x, c[i][j][1] + bv.y);
            float2 v1 = make_float2(c[i][j][2] + bv.x, c[i][j][3] + bv.y);
            *reinterpret_cast<float2*>(&C[(size_t)rm0 * VV + gn])       = v0;
            *reinterpret_cast<float2*>(&C[(size_t)(rm0 + 8) * VV + gn]) = v1;
        }
    }
}

// ---------------------------------------------------------------- mega kernel
// mode 0 (L0, 4 blocks): zero counters.
// mode 1 (L1, 8384 blocks):
//   bid [0,64)      : persistent rnn (512 steps); gated on g_zx0_done, releases g_rnn_done
//   bid [64,128)    : zx chunk 0      -> g_zx0_done
//   bid [128,320)   : zx chunks 1..3  -> g_zx_done
//   bid [320,384)   : embed cvt       -> g_cvt_done
//   bid [384,8384)  : gemm tile, gated on g_cvt_done==64 && g_rnn_done>=64*(chunk+1)
__global__ void __cluster_dims__(4, 1, 1) __launch_bounds__(256, 1)
mega_kernel(const float* __restrict__ hidden,
            const float* __restrict__ W1,
            const float* __restrict__ W2,
            const float* __restrict__ cls_b,
            const float* __restrict__ embed,
            const int*   __restrict__ ids,
            const float* __restrict__ b1,
            float* __restrict__ C,
            int mode) {
    const int bid = (int)blockIdx.x;
    const int tid = (int)threadIdx.x;

    if (mode == 0) {
        if (bid == 0 && tid == 0) {
            g_zx0_done = 0; g_zx_done = 0; g_cvt_done = 0; g_rnn_done = 0;
        }
        return;
    }

    if (bid < 64) {
        rnn_full(hidden, W1, W2);
    } else if (bid < 128) {
        zx_body(ids, embed, W1, b1, zx_token0(0, bid - 64));
        __syncthreads();
        if (tid == 0) red_rel(&g_zx0_done);
    } else if (bid < 320) {
        int j = bid - 128;
        zx_body(ids, embed, W1, b1, zx_token0(1 + j / 64, j % 64));
        __syncthreads();
        if (tid == 0) red_rel(&g_zx_done);
    } else if (bid < 384) {
        cvt_body(embed, bid - 320, 64);
        __syncthreads();
        if (tid == 0) red_rel(&g_cvt_done);
    } else {
        const int gb = bid - 384;
        const int chunk = gb / 2000;
        const int g = gb % 2000;
        if (tid == 0) {
            spin_until(&g_cvt_done, 64u);
            spin_until(&g_rnn_done, (unsigned)(64 * (chunk + 1)));
        }
        __syncthreads();
        gemm_body(cls_b, C, g, chunk);
    }
}

// ---------------------------------------------------------------- launch
extern "C" void kernel_launch(void* const* d_in, const int* in_sizes, int n_in,
                              void* d_out, int out_size) {
    const int*   ids    = (const int*)d_in[0];
    const float* hidden = (const float*)d_in[1];
    const float* embed  = (const float*)d_in[2];
    const float* W1     = (const float*)d_in[3];
    const float* b1     = (const float*)d_in[4];
    const float* W2     = (const float*)d_in[5];
    const float* cls_b  = (const float*)d_in[6];
    float* out = (float*)d_out;

    cudaFuncSetAttribute(mega_kernel, cudaFuncAttributeMaxDynamicSharedMemorySize, GSMEM);

    // L0: counter reset
    mega_kernel<<<4, 256, GSMEM>>>(hidden, W1, W2, cls_b, embed, ids, b1, out, 0);
    // L1: everything, flag-gated
    mega_kernel<<<8384, 256, GSMEM>>>(hidden, W1, W2, cls_b, embed, ids, b1, out, 1);
}

// round 16
// speedup vs baseline: 1.0050x; 1.0036x over previous
#include <cuda_runtime.h>
#include <cuda_fp16.h>
#include <cstdint>
#include <math.h>

#define VV   32000
#define EE   512
#define HH   512
#define MIDD 128
#define BB   16
#define SS   512

// scratch (device globals: no runtime allocation allowed)
__device__ float  g_Zx[BB * SS * MIDD];     // 4 MB
__device__ __half g_out16[BB * SS * EE];    // 8 MB
__device__ __half g_embed16[VV * EE];       // 32 MB
__device__ unsigned int g_zx0_done;         // 64 when zx chunk 0 written
__device__ unsigned int g_zx_done;          // 192 when zx chunks 1-3 written
__device__ unsigned int g_cvt_done;         // 64 when embed16 written
__device__ unsigned int g_rnn_done;         // +64 per completed 8-step group

// ---------------------------------------------------------------- helpers
__device__ __forceinline__ void cluster_sync_all() {
    asm volatile("barrier.cluster.arrive.aligned;" ::: "memory");
    asm volatile("barrier.cluster.wait.aligned;" ::: "memory");
}
__device__ __forceinline__ uint32_t mapa_rank(uint32_t saddr, uint32_t rank) {
    uint32_t pa;
    asm volatile("mapa.shared::cluster.u32 %0, %1, %2;" : "=r"(pa) : "r"(saddr), "r"(rank));
    return pa;
}
__device__ __forceinline__ void st_async_remote64(uint32_t daddr, unsigned long long v, uint32_t dbar) {
    asm volatile("st.async.shared::cluster.mbarrier::complete_tx::bytes.u64 [%0], %1, [%2];"
                 :: "r"(daddr), "l"(v), "r"(dbar) : "memory");
}
__device__ __forceinline__ void mbar_init(uint32_t a, uint32_t cnt) {
    asm volatile("mbarrier.init.shared.b64 [%0], %1;" :: "r"(a), "r"(cnt) : "memory");
}
__device__ __forceinline__ void mbar_expect_tx(uint32_t a, uint32_t bytes) {
    asm volatile("mbarrier.arrive.expect_tx.shared.b64 _, [%0], %1;"
                 :: "r"(a), "r"(bytes) : "memory");
}
__device__ __forceinline__ void mbar_wait(uint32_t a, uint32_t parity) {
    uint32_t done;
    asm volatile("{\n\t.reg .pred p;\n\t"
                 "mbarrier.try_wait.parity.acquire.cta.shared::cta.b64 p, [%1], %2;\n\t"
                 "selp.b32 %0, 1, 0, p;\n\t}"
                 : "=r"(done) : "r"(a), "r"(parity) : "memory");
    if (!done) {
        asm volatile("{\n\t.reg .pred P1;\n\t"
                     "WAIT_LOOP_%=:\n\t"
                     "mbarrier.try_wait.parity.acquire.cta.shared::cta.b64 P1, [%0], %1, 0x989680;\n\t"
                     "@P1 bra.uni WAIT_DONE_%=;\n\t"
                     "bra.uni WAIT_LOOP_%=;\n\t"
                     "WAIT_DONE_%=:\n\t}"
                     :: "r"(a), "r"(parity) : "memory");
    }
}
__device__ __forceinline__ void ldsm_x4(uint32_t& r0, uint32_t& r1, uint32_t& r2,
                                        uint32_t& r3, uint32_t a) {
    asm volatile("ldmatrix.sync.aligned.m8n8.x4.shared.b16 {%0,%1,%2,%3}, [%4];"
                 : "=r"(r0), "=r"(r1), "=r"(r2), "=r"(r3) : "r"(a));
}
__device__ __forceinline__ void mma16816(float* c, const uint32_t* a, uint32_t b0, uint32_t b1) {
    asm volatile("mma.sync.aligned.m16n8k16.row.col.f32.f16.f16.f32 "
                 "{%0,%1,%2,%3},{%4,%5,%6,%7},{%8,%9},{%0,%1,%2,%3};"
                 : "+f"(c[0]), "+f"(c[1]), "+f"(c[2]), "+f"(c[3])
                 : "r"(a[0]), "r"(a[1]), "r"(a[2]), "r"(a[3]), "r"(b0), "r"(b1));
}
__device__ __forceinline__ void cp16(uint32_t s, const void* g) {
    asm volatile("cp.async.cg.shared.global [%0], [%1], 16;" :: "r"(s), "l"(g));
}
__device__ __forceinline__ unsigned ld_acq(const unsigned* p) {
    unsigned v;
    asm volatile("ld.acquire.gpu.global.u32 %0, [%1];" : "=r"(v) : "l"(p) : "memory");
    return v;
}
__device__ __forceinline__ void red_rel(unsigned* p) {
    asm volatile("red.release.gpu.global.add.u32 [%0], 1;" :: "l"(p) : "memory");
}
__device__ __forceinline__ void spin_until(const unsigned* p, unsigned target) {
    while (ld_acq(p) < target) {
        asm volatile("nanosleep.u32 128;");
    }
}

// ---------------------------------------------------------------- zx body (256 thr; tid>=128 idles through barriers)
__device__ __forceinline__ void zx_body(const int* __restrict__ ids,
                                        const float* __restrict__ embed,
                                        const float* __restrict__ W1,
                                        const float* __restrict__ b1,
                                        int token0) {
    __shared__ float xs[32][64];
    __shared__ float ws[64][MIDD];
    __shared__ int   sid[32];
    const int tid = threadIdx.x;

    if (tid < 32) sid[tid] = ids[token0 + tid];
    __syncthreads();

    float acc[32];
#pragma unroll
    for (int m = 0; m < 32; m++) acc[m] = 0.f;

    for (int kt = 0; kt < 8; kt++) {
        const int k0 = kt * 64;
        if (tid < 128) {
#pragma unroll
            for (int i = 0; i < 4; i++) {
                int j = tid + i * 128, m = j >> 4, q = j & 15;
                *reinterpret_cast<float4*>(&xs[m][q * 4]) =
                    *reinterpret_cast<const float4*>(&embed[(size_t)sid[m] * EE + k0 + q * 4]);
            }
#pragma unroll
            for (int i = 0; i < 16; i++) {
                int j = tid + i * 128, k = j >> 5, q = j & 31;
                *reinterpret_cast<float4*>(&ws[k][q * 4]) =
                    *reinterpret_cast<const float4*>(&W1[(size_t)(k0 + k) * MIDD + q * 4]);
            }
        }
        __syncthreads();
        if (tid < 128) {
#pragma unroll 4
            for (int kk = 0; kk < 64; kk += 4) {
                float w0 = ws[kk + 0][tid], w1 = ws[kk + 1][tid];
                float w2 = ws[kk + 2][tid], w3 = ws[kk + 3][tid];
#pragma unroll
                for (int m = 0; m < 32; m++) {
                    float4 x4 = *reinterpret_cast<const float4*>(&xs[m][kk]);
                    float a = acc[m];
                    a = fmaf(x4.x, w0, a); a = fmaf(x4.y, w1, a);
                    a = fmaf(x4.z, w2, a); a = fmaf(x4.w, w3, a);
                    acc[m] = a;
                }
            }
        }
        __syncthreads();
    }
    if (tid < 128) {
        const float bb = b1[tid];
#pragma unroll
        for (int m = 0; m < 32; m++)
            g_Zx[(size_t)(token0 + m) * MIDD + tid] = acc[m] + bb;
    }
}

// zx chunk c covers t in [128c, 128c+128) for all 16 batches.
__device__ __forceinline__ int zx_token0(int chunk, int i) {
    return (i >> 2) * SS + chunk * 128 + (i & 3) * 32;
}

// ---------------------------------------------------------------- cvt body
__device__ __forceinline__ void cvt_body(const float* __restrict__ src, int bid, int nblocks) {
    int i = bid * (int)blockDim.x + (int)threadIdx.x;
    int stride = nblocks * (int)blockDim.x;
    const int n4 = (VV * EE) / 4;
    __half2* dst = reinterpret_cast<__half2*>(g_embed16);
    const float4* s4 = reinterpret_cast<const float4*>(src);
    for (; i < n4; i += stride) {
        float4 v = s4[i];
        dst[2 * i + 0] = __floats2half2_rn(v.x, v.y);
        dst[2 * i + 1] = __floats2half2_rn(v.z, v.w);
    }
}

// ---------------------------------------------------------------- persistent rnn body (512 steps, 256 thr)
#define NBUF 4
__device__ __forceinline__ void rnn_full(const float* __restrict__ hidden,
                                         const float* __restrict__ W1,
                                         const float* __restrict__ W2) {
    __shared__ __align__(16) float h_loc[128];
    __shared__ __align__(16) float g_s[128];
    __shared__ __align__(16) float zparts[NBUF][4][128];
    __shared__ __align__(8)  unsigned long long mbar[NBUF];

    const int tid  = threadIdx.x;
    const int b    = blockIdx.x >> 2;
    const int c    = tid >> 1;
    const int half = tid & 1;
    uint32_t rank;
    asm("mov.u32 %0, %%cluster_ctarank;" : "=r"(rank));

    float w1z[64], w2h[64];
#pragma unroll
    for (int i = 0; i < 64; i++)
        w1z[i] = W1[(size_t)(HH + 128 * rank + 64 * half + i) * MIDD + c];
#pragma unroll
    for (int i = 0; i < 64; i++)
        w2h[i] = W2[(size_t)(64 * half + i) * EE + 128 * rank + c];

    const uint32_t zp_loc  = (uint32_t)__cvta_generic_to_shared(&zparts[0][0][0]);
    const uint32_t bar_loc = (uint32_t)__cvta_generic_to_shared(&mbar[0]);

    if (tid == 0) {
#pragma unroll
        for (int s = 0; s < NBUF; s++) mbar_init(bar_loc + 8u * s, 1);
    }
    if (tid < 128) h_loc[tid] = hidden[(size_t)b * HH + 128 * rank + tid];
    __syncthreads();
    cluster_sync_all();

    uint32_t zp_dst[4], bar_dst[4];
#pragma unroll
    for (int r = 0; r < 4; r++) {
        zp_dst[r]  = mapa_rank(zp_loc, r);
        bar_dst[r] = mapa_rank(bar_loc, r);
    }

    // wait for zx chunk 0 before first read
    if (tid == 0) spin_until(&g_zx0_done, 64u);
    __syncthreads();

    const float* zx_row  = g_Zx    + (size_t)b * SS * MIDD;
    __half*      out_row = g_out16 + (size_t)b * SS * EE + 128 * rank;
    float zx_cur = (tid < 128) ? zx_row[tid] : 0.f;

    for (int t = 0; t < SS; t++) {
        const int buf = t & (NBUF - 1);
        const uint32_t ph = (uint32_t)((t >> 2) & 1);

        // gate before consuming zx chunks 1..3 (prefetch of t+1 happens this step)
        if (((t & 127) == 127) && t != 511) spin_until(&g_zx_done, 192u);

        if (tid == 0) mbar_expect_tx(bar_loc + 8u * buf, 4 * 128 * 4);

        float a0 = 0.f, a1 = 0.f, a2 = 0.f, a3 = 0.f;
#pragma unroll
        for (int i = 0; i < 64; i += 4) {
            float4 h4 = *reinterpret_cast<const float4*>(&h_loc[64 * half + i]);
            a0 = fmaf(h4.x, w1z[i + 0], a0);
            a1 = fmaf(h4.y, w1z[i + 1], a1);
            a2 = fmaf(h4.z, w1z[i + 2], a2);
            a3 = fmaf(h4.w, w1z[i + 3], a3);
        }
        float part = (a0 + a1) + (a2 + a3);
        part += __shfl_xor_sync(0xffffffffu, part, 1);
        float other = __shfl_xor_sync(0xffffffffu, part, 2);

        if ((tid & 3) == 0) {           // half==0 and c even
            unsigned long long pkt;
            asm("mov.b64 %0, {%1, %2};" : "=l"(pkt)
                : "r"(__float_as_uint(part)), "r"(__float_as_uint(other)));
            const uint32_t off = (uint32_t)((buf * 4 + rank) * 128 + c) * 4u;
#pragma unroll
            for (int r = 0; r < 4; r++)
                st_async_remote64(zp_dst[r] + off, pkt, bar_dst[r] + 8u * buf);
        }

        mbar_wait(bar_loc + 8u * buf, ph);

        if (tid < 128) {
            const float* zp = &zparts[buf][0][tid];
            float z = zx_cur + ((zp[0] + zp[128]) + (zp[256] + zp[384]));
            g_s[tid] = 0.5f * z * (1.0f + erff(z * 0.70710678118f));
            if (t + 1 < SS) zx_cur = zx_row[(size_t)(t + 1) * MIDD + tid];
        }
        __syncthreads();

        float b0 = 0.f, b1a = 0.f, b2 = 0.f, b3 = 0.f;
#pragma unroll
        for (int i = 0; i < 64; i += 4) {
            float4 g4 = *reinterpret_cast<const float4*>(&g_s[64 * half + i]);
            b0  = fmaf(g4.x, w2h[i + 0], b0);
            b1a = fmaf(g4.y, w2h[i + 1], b1a);
            b2  = fmaf(g4.z, w2h[i + 2], b2);
            b3  = fmaf(g4.w, w2h[i + 3], b3);
        }
        float hp = (b0 + b1a) + (b2 + b3);
        hp += __shfl_xor_sync(0xffffffffu, hp, 1);
        if (half == 0) {
            h_loc[c] = hp;
            out_row[(size_t)t * EE + c] = __float2half_rn(hp);
        }
        __syncthreads();

        // publish every 8 completed steps (stores ordered by the barrier above)
        if (((t & 7) == 7) && tid == 0) red_rel(&g_rnn_done);
    }
    cluster_sync_all();
}

// ---------------------------------------------------------------- gemm body — R8 engine, batch-interleaved row map
// Tile j covers global rows m in [128j, 128j+128) with m -> (t = m>>4, b = m&15).
// Output/input row index = b*SS + t. Tile j depends only on rnn t < 8(j+1).
#define ASTRIDE 72                       // halves per smem row (144B)
#define A_ST    (128 * ASTRIDE)
#define B_ST    (256 * ASTRIDE)
#define GSMEM   ((3 * (A_ST + B_ST)) * 2)   // 165888 B

__device__ __forceinline__ int row_of_m(int m) {
    return (m & 15) * SS + (m >> 4);
}

__device__ __forceinline__ void gemm_body(const float* __restrict__ cls_b,
                                          float* __restrict__ C,
                                          int tj, int nb) {
    extern __shared__ __align__(16) __half sm[];
    __half* As = sm;
    __half* Bs = sm + 3 * A_ST;

    const int tid = threadIdx.x;
    const int wid = tid >> 5, lane = tid & 31;
    const int M0 = tj * 128;
    const int N0 = nb * 256;

    const __half* Bg = g_embed16 + (size_t)N0 * EE;

    const int warp_m = (wid >> 2) * 64;
    const int warp_n = (wid & 3) * 64;

    float c[4][8][4];
#pragma unroll
    for (int i = 0; i < 4; i++)
#pragma unroll
        for (int j = 0; j < 8; j++)
#pragma unroll
            for (int q = 0; q < 4; q++) c[i][j][q] = 0.f;

    const uint32_t asb = (uint32_t)__cvta_generic_to_shared(As);
    const uint32_t bsb = (uint32_t)__cvta_generic_to_shared(Bs);

    auto load_tile = [&](int kt, int st) {
        const uint32_t ab = asb + (uint32_t)(st * A_ST) * 2;
        const uint32_t bb = bsb + (uint32_t)(st * B_ST) * 2;
#pragma unroll
        for (int i = 0; i < 4; i++) {           // A: 1024 chunks of 16B
            int cc = tid + i * 256;
            int r = cc >> 3, sg = cc & 7;
            const __half* arow = g_out16 + (size_t)row_of_m(M0 + r) * EE;
            cp16(ab + (uint32_t)(r * ASTRIDE + sg * 8) * 2,
                 arow + kt * 64 + sg * 8);
        }
#pragma unroll
        for (int i = 0; i < 8; i++) {           // B: 2048 chunks of 16B
            int cc = tid + i * 256;
            int r = cc >> 3, sg = cc & 7;
            cp16(bb + (uint32_t)(r * ASTRIDE + sg * 8) * 2,
                 Bg + (size_t)r * EE + kt * 64 + sg * 8);
        }
        asm volatile("cp.async.commit_group;");
    };

    uint32_t afr[2][4][4], bfr[2][8][2];

    auto ldsm_batch = [&](int kk, uint32_t ab, uint32_t bb, int pb) {
        const uint32_t koff = (uint32_t)(kk * 16 + ((lane >> 4) << 3));
#pragma unroll
        for (int i = 0; i < 4; i++) {
            uint32_t addr = ab + (uint32_t)((warp_m + i * 16 + (lane & 15)) * ASTRIDE + koff) * 2;
            ldsm_x4(afr[pb][i][0], afr[pb][i][1], afr[pb][i][2], afr[pb][i][3], addr);
        }
#pragma unroll
        for (int j2 = 0; j2 < 4; j2++) {
            uint32_t r0, r1, r2, r3;
            uint32_t addr = bb + (uint32_t)((warp_n + j2 * 16 + (lane & 15)) * ASTRIDE + koff) * 2;
            ldsm_x4(r0, r1, r2, r3, addr);
            bfr[pb][2 * j2 + 0][0] = r0; bfr[pb][2 * j2 + 0][1] = r2;
            bfr[pb][2 * j2 + 1][0] = r1; bfr[pb][2 * j2 + 1][1] = r3;
        }
    };

    load_tile(0, 0);
    load_tile(1, 1);

    for (int kt = 0; kt < 8; kt++) {
        const int st = kt % 3;
        if (kt < 7) asm volatile("cp.async.wait_group 1;");
        else        asm volatile("cp.async.wait_group 0;");
        __syncthreads();

        if (kt + 2 < 8) load_tile(kt + 2, (kt + 2) % 3);

        const uint32_t ab = asb + (uint32_t)(st * A_ST) * 2;
        const uint32_t bb = bsb + (uint32_t)(st * B_ST) * 2;

        ldsm_batch(0, ab, bb, 0);
#pragma unroll
        for (int kk = 0; kk < 4; kk++) {
            const int cur = kk & 1;
            if (kk < 3) ldsm_batch(kk + 1, ab, bb, cur ^ 1);
#pragma unroll
            for (int i = 0; i < 4; i++)
#pragma unroll
                for (int j = 0; j < 8; j++)
                    mma16816(c[i][j], afr[cur][i], bfr[cur][j][0], bfr[cur][j][1]);
        }
        __syncthreads();
    }

#pragma unroll
    for (int i = 0; i < 4; i++) {
        int m0 = M0 + warp_m + i * 16 + (lane >> 2);
        int rm0 = row_of_m(m0);
        int rm1 = row_of_m(m0 + 8);
#pragma unroll
        for (int j = 0; j < 8; j++) {
            int gn = N0 + warp_n + j * 8 + (lane & 3) * 2;
            float2 bv = *reinterpret_cast<const float2*>(&cls_b[gn]);
            float2 v0 = make_float2(c[i][j][0] + bv.x, c[i][j][1] + bv.y);
            float2 v1 = make_float2(c[i][j][2] + bv.x, c[i][j][3] + bv.y);
            *reinterpret_cast<float2*>(&C[(size_t)rm0 * VV + gn]) = v0;
            *reinterpret_cast<float2*>(&C[(size_t)rm1 * VV + gn]) = v1;
        }
    }
}

// ---------------------------------------------------------------- mega kernel
// mode 0 (L0, 4 blocks): zero counters.
// mode 1 (L1, 8384 blocks):
//   bid [0,64)      : persistent rnn; gated on zx counters, releases g_rnn_done per 8 steps
//   bid [64,128)    : zx chunk 0      -> g_zx0_done
//   bid [128,320)   : zx chunks 1..3  -> g_zx_done
//   bid [320,384)   : embed cvt       -> g_cvt_done
//   bid [384,8384)  : gemm tile (tj = gb/125, nb = gb%125),
//                     gated on g_cvt_done==64 && g_rnn_done >= 64*(tj+1)
__global__ void __cluster_dims__(4, 1, 1) __launch_bounds__(256, 1)
mega_kernel(const float* __restrict__ hidden,
            const float* __restrict__ W1,
            const float* __restrict__ W2,
            const float* __restrict__ cls_b,
            const float* __restrict__ embed,
            const int*   __restrict__ ids,
            const float* __restrict__ b1,
            float* __restrict__ C,
            int mode) {
    const int bid = (int)blockIdx.x;
    const int tid = (int)threadIdx.x;

    if (mode == 0) {
        if (bid == 0 && tid == 0) {
            g_zx0_done = 0; g_zx_done = 0; g_cvt_done = 0; g_rnn_done = 0;
        }
        return;
    }

    if (bid < 64) {
        rnn_full(hidden, W1, W2);
    } else if (bid < 128) {
        zx_body(ids, embed, W1, b1, zx_token0(0, bid - 64));
        __syncthreads();
        if (tid == 0) red_rel(&g_zx0_done);
    } else if (bid < 320) {
        int j = bid - 128;
        zx_body(ids, embed, W1, b1, zx_token0(1 + j / 64, j % 64));
        __syncthreads();
        if (tid == 0) red_rel(&g_zx_done);
    } else if (bid < 384) {
        cvt_body(embed, bid - 320, 64);
        __syncthreads();
        if (tid == 0) red_rel(&g_cvt_done);
    } else {
        const int gb = bid - 384;
        const int tj = gb / 125;
        const int nb = gb % 125;
        if (tid == 0) {
            spin_until(&g_cvt_done, 64u);
            spin_until(&g_rnn_done, (unsigned)(64 * (tj + 1)));
        }
        __syncthreads();
        gemm_body(cls_b, C, tj, nb);
    }
}

// ---------------------------------------------------------------- launch
extern "C" void kernel_launch(void* const* d_in, const int* in_sizes, int n_in,
                              void* d_out, int out_size) {
    const int*   ids    = (const int*)d_in[0];
    const float* hidden = (const float*)d_in[1];
    const float* embed  = (const float*)d_in[2];
    const float* W1     = (const float*)d_in[3];
    const float* b1     = (const float*)d_in[4];
    const float* W2     = (const float*)d_in[5];
    const float* cls_b  = (const float*)d_in[6];
    float* out = (float*)d_out;

    cudaFuncSetAttribute(mega_kernel, cudaFuncAttributeMaxDynamicSharedMemorySize, GSMEM);

    // L0: counter reset
    mega_kernel<<<4, 256, GSMEM>>>(hidden, W1, W2, cls_b, embed, ids, b1, out, 0);
    // L1: everything, flag-gated
    mega_kernel<<<8384, 256, GSMEM>>>(hidden, W1, W2, cls_b, embed, ids, b1, out, 1);
}

// round 17
// speedup vs baseline: 1.0062x; 1.0012x over previous
#include <cuda_runtime.h>
#include <cuda_fp16.h>
#include <cstdint>
#include <math.h>

#define VV   32000
#define EE   512
#define HH   512
#define MIDD 128
#define BB   16
#define SS   512

// scratch (device globals: no runtime allocation allowed)
__device__ float  g_Zx[BB * SS * MIDD];     // 4 MB
__device__ __half g_out16[BB * SS * EE];    // 8 MB
__device__ __half g_embed16[VV * EE];       // 32 MB
__device__ unsigned int g_zx0_done;         // 64 when zx chunk 0 written
__device__ unsigned int g_zx_done;          // 192 when zx chunks 1-3 written
__device__ unsigned int g_rnn_done;         // +64 per completed 8-step group
__device__ unsigned int g_cvt_flag[64];     // 1 when vocab slab s converted

// ---------------------------------------------------------------- helpers
__device__ __forceinline__ void cluster_sync_all() {
    asm volatile("barrier.cluster.arrive.aligned;" ::: "memory");
    asm volatile("barrier.cluster.wait.aligned;" ::: "memory");
}
__device__ __forceinline__ uint32_t mapa_rank(uint32_t saddr, uint32_t rank) {
    uint32_t pa;
    asm volatile("mapa.shared::cluster.u32 %0, %1, %2;" : "=r"(pa) : "r"(saddr), "r"(rank));
    return pa;
}
__device__ __forceinline__ void st_async_remote64(uint32_t daddr, unsigned long long v, uint32_t dbar) {
    asm volatile("st.async.shared::cluster.mbarrier::complete_tx::bytes.u64 [%0], %1, [%2];"
                 :: "r"(daddr), "l"(v), "r"(dbar) : "memory");
}
__device__ __forceinline__ void mbar_init(uint32_t a, uint32_t cnt) {
    asm volatile("mbarrier.init.shared.b64 [%0], %1;" :: "r"(a), "r"(cnt) : "memory");
}
__device__ __forceinline__ void mbar_expect_tx(uint32_t a, uint32_t bytes) {
    asm volatile("mbarrier.arrive.expect_tx.shared.b64 _, [%0], %1;"
                 :: "r"(a), "r"(bytes) : "memory");
}
__device__ __forceinline__ void mbar_wait(uint32_t a, uint32_t parity) {
    uint32_t done;
    asm volatile("{\n\t.reg .pred p;\n\t"
                 "mbarrier.try_wait.parity.acquire.cta.shared::cta.b64 p, [%1], %2;\n\t"
                 "selp.b32 %0, 1, 0, p;\n\t}"
                 : "=r"(done) : "r"(a), "r"(parity) : "memory");
    if (!done) {
        asm volatile("{\n\t.reg .pred P1;\n\t"
                     "WAIT_LOOP_%=:\n\t"
                     "mbarrier.try_wait.parity.acquire.cta.shared::cta.b64 P1, [%0], %1, 0x989680;\n\t"
                     "@P1 bra.uni WAIT_DONE_%=;\n\t"
                     "bra.uni WAIT_LOOP_%=;\n\t"
                     "WAIT_DONE_%=:\n\t}"
                     :: "r"(a), "r"(parity) : "memory");
    }
}
__device__ __forceinline__ void ldsm_x4(uint32_t& r0, uint32_t& r1, uint32_t& r2,
                                        uint32_t& r3, uint32_t a) {
    asm volatile("ldmatrix.sync.aligned.m8n8.x4.shared.b16 {%0,%1,%2,%3}, [%4];"
                 : "=r"(r0), "=r"(r1), "=r"(r2), "=r"(r3) : "r"(a));
}
__device__ __forceinline__ void mma16816(float* c, const uint32_t* a, uint32_t b0, uint32_t b1) {
    asm volatile("mma.sync.aligned.m16n8k16.row.col.f32.f16.f16.f32 "
                 "{%0,%1,%2,%3},{%4,%5,%6,%7},{%8,%9},{%0,%1,%2,%3};"
                 : "+f"(c[0]), "+f"(c[1]), "+f"(c[2]), "+f"(c[3])
                 : "r"(a[0]), "r"(a[1]), "r"(a[2]), "r"(a[3]), "r"(b0), "r"(b1));
}
__device__ __forceinline__ void cp16(uint32_t s, const void* g) {
    asm volatile("cp.async.cg.shared.global [%0], [%1], 16;" :: "r"(s), "l"(g));
}
__device__ __forceinline__ unsigned ld_acq(const unsigned* p) {
    unsigned v;
    asm volatile("ld.acquire.gpu.global.u32 %0, [%1];" : "=r"(v) : "l"(p) : "memory");
    return v;
}
__device__ __forceinline__ void red_rel(unsigned* p) {
    asm volatile("red.release.gpu.global.add.u32 [%0], 1;" :: "l"(p) : "memory");
}
__device__ __forceinline__ void spin_until(const unsigned* p, unsigned target) {
    while (ld_acq(p) < target) {
        asm volatile("nanosleep.u32 128;");
    }
}

// ---------------------------------------------------------------- zx body (256 thr; tid>=128 idles through barriers)
__device__ __forceinline__ void zx_body(const int* __restrict__ ids,
                                        const float* __restrict__ embed,
                                        const float* __restrict__ W1,
                                        const float* __restrict__ b1,
                                        int token0) {
    __shared__ float xs[32][64];
    __shared__ float ws[64][MIDD];
    __shared__ int   sid[32];
    const int tid = threadIdx.x;

    if (tid < 32) sid[tid] = ids[token0 + tid];
    __syncthreads();

    float acc[32];
#pragma unroll
    for (int m = 0; m < 32; m++) acc[m] = 0.f;

    for (int kt = 0; kt < 8; kt++) {
        const int k0 = kt * 64;
        if (tid < 128) {
#pragma unroll
            for (int i = 0; i < 4; i++) {
                int j = tid + i * 128, m = j >> 4, q = j & 15;
                *reinterpret_cast<float4*>(&xs[m][q * 4]) =
                    *reinterpret_cast<const float4*>(&embed[(size_t)sid[m] * EE + k0 + q * 4]);
            }
#pragma unroll
            for (int i = 0; i < 16; i++) {
                int j = tid + i * 128, k = j >> 5, q = j & 31;
                *reinterpret_cast<float4*>(&ws[k][q * 4]) =
                    *reinterpret_cast<const float4*>(&W1[(size_t)(k0 + k) * MIDD + q * 4]);
            }
        }
        __syncthreads();
        if (tid < 128) {
#pragma unroll 4
            for (int kk = 0; kk < 64; kk += 4) {
                float w0 = ws[kk + 0][tid], w1 = ws[kk + 1][tid];
                float w2 = ws[kk + 2][tid], w3 = ws[kk + 3][tid];
#pragma unroll
                for (int m = 0; m < 32; m++) {
                    float4 x4 = *reinterpret_cast<const float4*>(&xs[m][kk]);
                    float a = acc[m];
                    a = fmaf(x4.x, w0, a); a = fmaf(x4.y, w1, a);
                    a = fmaf(x4.z, w2, a); a = fmaf(x4.w, w3, a);
                    acc[m] = a;
                }
            }
        }
        __syncthreads();
    }
    if (tid < 128) {
        const float bb = b1[tid];
#pragma unroll
        for (int m = 0; m < 32; m++)
            g_Zx[(size_t)(token0 + m) * MIDD + tid] = acc[m] + bb;
    }
}

// zx chunk c covers t in [128c, 128c+128) for all 16 batches.
__device__ __forceinline__ int zx_token0(int chunk, int i) {
    return (i >> 2) * SS + chunk * 128 + (i & 3) * 32;
}

// ---------------------------------------------------------------- cvt slab: vocab rows [500s, 500s+500)
__device__ __forceinline__ void cvt_slab(const float* __restrict__ src, int s) {
    const int tid = (int)threadIdx.x;
    const size_t base4 = (size_t)s * 500 * EE / 4;      // float4 index
    const int n4 = 500 * EE / 4;                        // 64000 float4 per slab
    __half2* dst = reinterpret_cast<__half2*>(g_embed16);
    const float4* s4 = reinterpret_cast<const float4*>(src);
    for (int i = tid; i < n4; i += 256) {
        float4 v = s4[base4 + i];
        dst[2 * (base4 + i) + 0] = __floats2half2_rn(v.x, v.y);
        dst[2 * (base4 + i) + 1] = __floats2half2_rn(v.z, v.w);
    }
}

// ---------------------------------------------------------------- persistent rnn body (512 steps, 256 thr)
#define NBUF 4
__device__ __forceinline__ void rnn_full(const float* __restrict__ hidden,
                                         const float* __restrict__ W1,
                                         const float* __restrict__ W2) {
    __shared__ __align__(16) float h_loc[128];
    __shared__ __align__(16) float g_s[128];
    __shared__ __align__(16) float zparts[NBUF][4][128];
    __shared__ __align__(8)  unsigned long long mbar[NBUF];

    const int tid  = threadIdx.x;
    const int b    = blockIdx.x >> 2;
    const int c    = tid >> 1;
    const int half = tid & 1;
    uint32_t rank;
    asm("mov.u32 %0, %%cluster_ctarank;" : "=r"(rank));

    float w1z[64], w2h[64];
#pragma unroll
    for (int i = 0; i < 64; i++)
        w1z[i] = W1[(size_t)(HH + 128 * rank + 64 * half + i) * MIDD + c];
#pragma unroll
    for (int i = 0; i < 64; i++)
        w2h[i] = W2[(size_t)(64 * half + i) * EE + 128 * rank + c];

    const uint32_t zp_loc  = (uint32_t)__cvta_generic_to_shared(&zparts[0][0][0]);
    const uint32_t bar_loc = (uint32_t)__cvta_generic_to_shared(&mbar[0]);

    if (tid == 0) {
#pragma unroll
        for (int s = 0; s < NBUF; s++) mbar_init(bar_loc + 8u * s, 1);
    }
    if (tid < 128) h_loc[tid] = hidden[(size_t)b * HH + 128 * rank + tid];
    __syncthreads();
    cluster_sync_all();

    uint32_t zp_dst[4], bar_dst[4];
#pragma unroll
    for (int r = 0; r < 4; r++) {
        zp_dst[r]  = mapa_rank(zp_loc, r);
        bar_dst[r] = mapa_rank(bar_loc, r);
    }

    // wait for zx chunk 0 before first read
    if (tid == 0) spin_until(&g_zx0_done, 64u);
    __syncthreads();

    const float* zx_row  = g_Zx    + (size_t)b * SS * MIDD;
    __half*      out_row = g_out16 + (size_t)b * SS * EE + 128 * rank;
    float zx_cur = (tid < 128) ? zx_row[tid] : 0.f;

    for (int t = 0; t < SS; t++) {
        const int buf = t & (NBUF - 1);
        const uint32_t ph = (uint32_t)((t >> 2) & 1);

        // gate before consuming zx chunks 1..3 (prefetch of t+1 happens this step)
        if (((t & 127) == 127) && t != 511) spin_until(&g_zx_done, 192u);

        if (tid == 0) mbar_expect_tx(bar_loc + 8u * buf, 4 * 128 * 4);

        float a0 = 0.f, a1 = 0.f, a2 = 0.f, a3 = 0.f;
#pragma unroll
        for (int i = 0; i < 64; i += 4) {
            float4 h4 = *reinterpret_cast<const float4*>(&h_loc[64 * half + i]);
            a0 = fmaf(h4.x, w1z[i + 0], a0);
            a1 = fmaf(h4.y, w1z[i + 1], a1);
            a2 = fmaf(h4.z, w1z[i + 2], a2);
            a3 = fmaf(h4.w, w1z[i + 3], a3);
        }
        float part = (a0 + a1) + (a2 + a3);
        part += __shfl_xor_sync(0xffffffffu, part, 1);
        float other = __shfl_xor_sync(0xffffffffu, part, 2);

        if ((tid & 3) == 0) {           // half==0 and c even
            unsigned long long pkt;
            asm("mov.b64 %0, {%1, %2};" : "=l"(pkt)
                : "r"(__float_as_uint(part)), "r"(__float_as_uint(other)));
            const uint32_t off = (uint32_t)((buf * 4 + rank) * 128 + c) * 4u;
#pragma unroll
            for (int r = 0; r < 4; r++)
                st_async_remote64(zp_dst[r] + off, pkt, bar_dst[r] + 8u * buf);
        }

        mbar_wait(bar_loc + 8u * buf, ph);

        if (tid < 128) {
            const float* zp = &zparts[buf][0][tid];
            float z = zx_cur + ((zp[0] + zp[128]) + (zp[256] + zp[384]));
            g_s[tid] = 0.5f * z * (1.0f + erff(z * 0.70710678118f));
            if (t + 1 < SS) zx_cur = zx_row[(size_t)(t + 1) * MIDD + tid];
        }
        __syncthreads();

        float b0 = 0.f, b1a = 0.f, b2 = 0.f, b3 = 0.f;
#pragma unroll
        for (int i = 0; i < 64; i += 4) {
            float4 g4 = *reinterpret_cast<const float4*>(&g_s[64 * half + i]);
            b0  = fmaf(g4.x, w2h[i + 0], b0);
            b1a = fmaf(g4.y, w2h[i + 1], b1a);
            b2  = fmaf(g4.z, w2h[i + 2], b2);
            b3  = fmaf(g4.w, w2h[i + 3], b3);
        }
        float hp = (b0 + b1a) + (b2 + b3);
        hp += __shfl_xor_sync(0xffffffffu, hp, 1);
        if (half == 0) {
            h_loc[c] = hp;
            out_row[(size_t)t * EE + c] = __float2half_rn(hp);
        }
        __syncthreads();

        // publish every 8 completed steps (stores ordered by the barrier above)
        if (((t & 7) == 7) && tid == 0) red_rel(&g_rnn_done);
    }
    cluster_sync_all();
}

// ---------------------------------------------------------------- gemm body — R8 engine, batch-interleaved row map
// Tile j covers global rows m in [128j, 128j+128) with m -> (t = m>>4, b = m&15).
#define ASTRIDE 72                       // halves per smem row (144B)
#define A_ST    (128 * ASTRIDE)
#define B_ST    (256 * ASTRIDE)
#define GSMEM   ((3 * (A_ST + B_ST)) * 2)   // 165888 B

__device__ __forceinline__ int row_of_m(int m) {
    return (m & 15) * SS + (m >> 4);
}

__device__ __forceinline__ void gemm_body(const float* __restrict__ cls_b,
                                          float* __restrict__ C,
                                          int tj, int nb) {
    extern __shared__ __align__(16) __half sm[];
    __half* As = sm;
    __half* Bs = sm + 3 * A_ST;

    const int tid = threadIdx.x;
    const int wid = tid >> 5, lane = tid & 31;
    const int M0 = tj * 128;
    const int N0 = nb * 256;

    const __half* Bg = g_embed16 + (size_t)N0 * EE;

    const int warp_m = (wid >> 2) * 64;
    const int warp_n = (wid & 3) * 64;

    float c[4][8][4];
#pragma unroll
    for (int i = 0; i < 4; i++)
#pragma unroll
        for (int j = 0; j < 8; j++)
#pragma unroll
            for (int q = 0; q < 4; q++) c[i][j][q] = 0.f;

    const uint32_t asb = (uint32_t)__cvta_generic_to_shared(As);
    const uint32_t bsb = (uint32_t)__cvta_generic_to_shared(Bs);

    auto load_tile = [&](int kt, int st) {
        const uint32_t ab = asb + (uint32_t)(st * A_ST) * 2;
        const uint32_t bb = bsb + (uint32_t)(st * B_ST) * 2;
#pragma unroll
        for (int i = 0; i < 4; i++) {           // A: 1024 chunks of 16B
            int cc = tid + i * 256;
            int r = cc >> 3, sg = cc & 7;
            const __half* arow = g_out16 + (size_t)row_of_m(M0 + r) * EE;
            cp16(ab + (uint32_t)(r * ASTRIDE + sg * 8) * 2,
                 arow + kt * 64 + sg * 8);
        }
#pragma unroll
        for (int i = 0; i < 8; i++) {           // B: 2048 chunks of 16B
            int cc = tid + i * 256;
            int r = cc >> 3, sg = cc & 7;
            cp16(bb + (uint32_t)(r * ASTRIDE + sg * 8) * 2,
                 Bg + (size_t)r * EE + kt * 64 + sg * 8);
        }
        asm volatile("cp.async.commit_group;");
    };

    uint32_t afr[2][4][4], bfr[2][8][2];

    auto ldsm_batch = [&](int kk, uint32_t ab, uint32_t bb, int pb) {
        const uint32_t koff = (uint32_t)(kk * 16 + ((lane >> 4) << 3));
#pragma unroll
        for (int i = 0; i < 4; i++) {
            uint32_t addr = ab + (uint32_t)((warp_m + i * 16 + (lane & 15)) * ASTRIDE + koff) * 2;
            ldsm_x4(afr[pb][i][0], afr[pb][i][1], afr[pb][i][2], afr[pb][i][3], addr);
        }
#pragma unroll
        for (int j2 = 0; j2 < 4; j2++) {
            uint32_t r0, r1, r2, r3;
            uint32_t addr = bb + (uint32_t)((warp_n + j2 * 16 + (lane & 15)) * ASTRIDE + koff) * 2;
            ldsm_x4(r0, r1, r2, r3, addr);
            bfr[pb][2 * j2 + 0][0] = r0; bfr[pb][2 * j2 + 0][1] = r2;
            bfr[pb][2 * j2 + 1][0] = r1; bfr[pb][2 * j2 + 1][1] = r3;
        }
    };

    load_tile(0, 0);
    load_tile(1, 1);

    for (int kt = 0; kt < 8; kt++) {
        const int st = kt % 3;
        if (kt < 7) asm volatile("cp.async.wait_group 1;");
        else        asm volatile("cp.async.wait_group 0;");
        __syncthreads();

        if (kt + 2 < 8) load_tile(kt + 2, (kt + 2) % 3);

        const uint32_t ab = asb + (uint32_t)(st * A_ST) * 2;
        const uint32_t bb = bsb + (uint32_t)(st * B_ST) * 2;

        ldsm_batch(0, ab, bb, 0);
#pragma unroll
        for (int kk = 0; kk < 4; kk++) {
            const int cur = kk & 1;
            if (kk < 3) ldsm_batch(kk + 1, ab, bb, cur ^ 1);
#pragma unroll
            for (int i = 0; i < 4; i++)
#pragma unroll
                for (int j = 0; j < 8; j++)
                    mma16816(c[i][j], afr[cur][i], bfr[cur][j][0], bfr[cur][j][1]);
        }
        __syncthreads();
    }

#pragma unroll
    for (int i = 0; i < 4; i++) {
        int m0 = M0 + warp_m + i * 16 + (lane >> 2);
        int rm0 = row_of_m(m0);
        int rm1 = row_of_m(m0 + 8);
#pragma unroll
        for (int j = 0; j < 8; j++) {
            int gn = N0 + warp_n + j * 8 + (lane & 3) * 2;
            float2 bv = *reinterpret_cast<const float2*>(&cls_b[gn]);
            float2 v0 = make_float2(c[i][j][0] + bv.x, c[i][j][1] + bv.y);
            float2 v1 = make_float2(c[i][j][2] + bv.x, c[i][j][3] + bv.y);
            *reinterpret_cast<float2*>(&C[(size_t)rm0 * VV + gn]) = v0;
            *reinterpret_cast<float2*>(&C[(size_t)rm1 * VV + gn]) = v1;
        }
    }
}

// ---------------------------------------------------------------- mega kernel
// mode 0 (L0, 4 blocks): zero counters + flags.
// mode 1 (L1, 8384 blocks):
//   bid [0,64)      : persistent rnn; releases g_rnn_done per 8 steps
//   bid [64,128)    : zx chunk 0      -> g_zx0_done
//   bid [128,192)   : cvt slab (bid-128) -> g_cvt_flag[s]
//   bid [192,384)   : zx chunks 1..3  -> g_zx_done
//   bid [384,8384)  : gemm tile (tj = gb/125, nb = gb%125),
//                     gated on cvt slabs covering its B rows && g_rnn_done >= 64*(tj+1)
__global__ void __cluster_dims__(4, 1, 1) __launch_bounds__(256, 1)
mega_kernel(const float* __restrict__ hidden,
            const float* __restrict__ W1,
            const float* __restrict__ W2,
            const float* __restrict__ cls_b,
            const float* __restrict__ embed,
            const int*   __restrict__ ids,
            const float* __restrict__ b1,
            float* __restrict__ C,
            int mode) {
    const int bid = (int)blockIdx.x;
    const int tid = (int)threadIdx.x;

    if (mode == 0) {
        if (bid == 0) {
            if (tid == 0) { g_zx0_done = 0; g_zx_done = 0; g_rnn_done = 0; }
            if (tid < 64) g_cvt_flag[tid] = 0;
        }
        return;
    }

    if (bid < 64) {
        rnn_full(hidden, W1, W2);
    } else if (bid < 128) {
        zx_body(ids, embed, W1, b1, zx_token0(0, bid - 64));
        __syncthreads();
        if (tid == 0) red_rel(&g_zx0_done);
    } else if (bid < 192) {
        const int s = bid - 128;
        cvt_slab(embed, s);
        __syncthreads();
        if (tid == 0) red_rel(&g_cvt_flag[s]);
    } else if (bid < 384) {
        int j = bid - 192;
        zx_body(ids, embed, W1, b1, zx_token0(1 + j / 64, j % 64));
        __syncthreads();
        if (tid == 0) red_rel(&g_zx_done);
    } else {
        const int gb = bid - 384;
        const int tj = gb / 125;
        const int nb = gb % 125;
        if (tid == 0) {
            const int s0 = (256 * nb) / 500;
            const int s1 = (256 * nb + 255) / 500;
            spin_until(&g_cvt_flag[s0], 1u);
            if (s1 != s0) spin_until(&g_cvt_flag[s1], 1u);
            spin_until(&g_rnn_done, (unsigned)(64 * (tj + 1)));
        }
        __syncthreads();
        gemm_body(cls_b, C, tj, nb);
    }
}

// ---------------------------------------------------------------- launch
extern "C" void kernel_launch(void* const* d_in, const int* in_sizes, int n_in,
                              void* d_out, int out_size) {
    const int*   ids    = (const int*)d_in[0];
    const float* hidden = (const float*)d_in[1];
    const float* embed  = (const float*)d_in[2];
    const float* W1     = (const float*)d_in[3];
    const float* b1     = (const float*)d_in[4];
    const float* W2     = (const float*)d_in[5];
    const float* cls_b  = (const float*)d_in[6];
    float* out = (float*)d_out;

    cudaFuncSetAttribute(mega_kernel, cudaFuncAttributeMaxDynamicSharedMemorySize, GSMEM);

    // L0: counter/flag reset
    mega_kernel<<<4, 256, GSMEM>>>(hidden, W1, W2, cls_b, embed, ids, b1, out, 0);
    // L1: everything, flag-gated
    mega_kernel<<<8384, 256, GSMEM>>>(hidden, W1, W2, cls_b, embed, ids, b1, out, 1);
}